// round 17
// baseline (speedup 1.0000x reference)
#include <cuda_runtime.h>
#include <cuda_bf16.h>
#include <math.h>
#include <stdint.h>

// Problem constants (b=1, c=512, t=16, h=w=32)
#define C_DIM 512
#define T_FR 16
#define HW 1024          // h*w tokens per frame
#define S_TOT 16384      // t*h*w
#define NG 32            // groups
#define CPG 16           // channels per group

typedef __nv_bfloat16 bf16;
typedef __nv_bfloat162 bf162;

// ---------------- scratch (device globals; no allocation allowed) ----------
__device__ __align__(16) bf16  g_hn[S_TOT * C_DIM];        // token-major [s][c]
__device__ __align__(16) bf16  g_q [S_TOT * C_DIM];        // [s][c]
__device__ __align__(16) bf16  g_k [S_TOT * C_DIM];        // [s][c]
__device__ __align__(16) bf16  g_v [S_TOT * C_DIM];        // [s][c]
__device__ __align__(16) float g_p [T_FR * HW * HW];       // [f][i][j] fp32 scores
__device__ __align__(16) bf16  g_pb[T_FR * HW * HW];       // bf16 probs
__device__ __align__(16) bf16  g_ao[S_TOT * C_DIM];        // [s][c]
__device__ __align__(16) bf16  g_wq[C_DIM * C_DIM];
__device__ __align__(16) bf16  g_wk[C_DIM * C_DIM];
__device__ __align__(16) bf16  g_wv[C_DIM * C_DIM];
__device__ __align__(16) bf16  g_wo[C_DIM * C_DIM];
__device__ float g_part[NG * 8 * 2];
__device__ float g_mean[NG];
__device__ float g_rstd[NG];

// ======================= elementwise kernels ================================

__global__ void w_convert(const float* __restrict__ w0, const float* __restrict__ w1,
                          const float* __restrict__ w2, const float* __restrict__ w3) {
    const float* src; bf16* dst;
    if (blockIdx.y == 0)      { src = w0; dst = g_wq; }
    else if (blockIdx.y == 1) { src = w1; dst = g_wk; }
    else if (blockIdx.y == 2) { src = w2; dst = g_wv; }
    else                      { src = w3; dst = g_wo; }
    int i = blockIdx.x * 256 + threadIdx.x;
    float4 v = reinterpret_cast<const float4*>(src)[i];
    bf162* d = reinterpret_cast<bf162*>(dst) + i * 2;
    d[0] = __float22bfloat162_rn(make_float2(v.x, v.y));
    d[1] = __float22bfloat162_rn(make_float2(v.z, v.w));
}

__global__ void gn_stats1(const float* __restrict__ x) {
    const int g = blockIdx.x;
    const int chunk = blockIdx.y;
    const int n_chunk = (CPG * S_TOT) / 8;
    const float* xp = x + (size_t)g * CPG * S_TOT + (size_t)chunk * n_chunk;
    float s = 0.f, ss = 0.f;
    for (int i = threadIdx.x; i < n_chunk / 4; i += 256) {
        float4 v = reinterpret_cast<const float4*>(xp)[i];
        s  += v.x + v.y + v.z + v.w;
        ss += v.x * v.x + v.y * v.y + v.z * v.z + v.w * v.w;
    }
    #pragma unroll
    for (int o = 16; o > 0; o >>= 1) {
        s  += __shfl_xor_sync(0xffffffffu, s, o);
        ss += __shfl_xor_sync(0xffffffffu, ss, o);
    }
    __shared__ float rs[8], rss[8];
    if ((threadIdx.x & 31) == 0) { rs[threadIdx.x >> 5] = s; rss[threadIdx.x >> 5] = ss; }
    __syncthreads();
    if (threadIdx.x == 0) {
        float ts = 0.f, tss = 0.f;
        #pragma unroll
        for (int i = 0; i < 8; i++) { ts += rs[i]; tss += rss[i]; }
        g_part[(g * 8 + chunk) * 2 + 0] = ts;
        g_part[(g * 8 + chunk) * 2 + 1] = tss;
    }
}

__global__ void gn_stats2() {
    int g = threadIdx.x;
    if (g >= NG) return;
    float s = 0.f, ss = 0.f;
    #pragma unroll
    for (int i = 0; i < 8; i++) {
        s  += g_part[(g * 8 + i) * 2 + 0];
        ss += g_part[(g * 8 + i) * 2 + 1];
    }
    const float inv_n = 1.0f / (float)(CPG * S_TOT);
    float m = s * inv_n;
    float var = ss * inv_n - m * m;
    g_mean[g] = m;
    g_rstd[g] = rsqrtf(var + 1e-6f);
}

__global__ void gn_apply_t(const float* __restrict__ x,
                           const float* __restrict__ gamma,
                           const float* __restrict__ beta) {
    __shared__ float tile[32][33];
    const int s0 = blockIdx.x * 32;
    const int c0 = blockIdx.y * 32;
    const int tx = threadIdx.x, ty = threadIdx.y;
    #pragma unroll
    for (int j = 0; j < 4; j++) {
        int cl = ty + j * 8;
        tile[cl][tx] = x[(size_t)(c0 + cl) * S_TOT + s0 + tx];
    }
    __syncthreads();
    int c = c0 + tx;
    int g = c >> 4;
    float m = g_mean[g], r = g_rstd[g];
    float ga = gamma[c], be = beta[c];
    #pragma unroll
    for (int j = 0; j < 4; j++) {
        int sl = ty + j * 8;
        g_hn[(size_t)(s0 + sl) * C_DIM + c] =
            __float2bfloat16_rn((tile[tx][sl] - m) * r * ga + be);
    }
}

__global__ void softmax_rows() {
    const int row = blockIdx.x;
    const float4* p4 = reinterpret_cast<const float4*>(g_p + (size_t)row * HW);
    const int tid  = threadIdx.x;
    const int lane = tid & 31;
    const int wid  = tid >> 5;
    __shared__ float red[8];

    float4 v = p4[tid];
    float mx = fmaxf(fmaxf(v.x, v.y), fmaxf(v.z, v.w));
    #pragma unroll
    for (int o = 16; o > 0; o >>= 1) mx = fmaxf(mx, __shfl_xor_sync(0xffffffffu, mx, o));
    if (lane == 0) red[wid] = mx;
    __syncthreads();
    mx = red[lane & 7];
    #pragma unroll
    for (int o = 4; o > 0; o >>= 1) mx = fmaxf(mx, __shfl_xor_sync(0xffffffffu, mx, o));

    v.x = __expf(v.x - mx); v.y = __expf(v.y - mx);
    v.z = __expf(v.z - mx); v.w = __expf(v.w - mx);
    float s = v.x + v.y + v.z + v.w;
    #pragma unroll
    for (int o = 16; o > 0; o >>= 1) s += __shfl_xor_sync(0xffffffffu, s, o);
    __syncthreads();
    if (lane == 0) red[wid] = s;
    __syncthreads();
    s = red[lane & 7];
    #pragma unroll
    for (int o = 4; o > 0; o >>= 1) s += __shfl_xor_sync(0xffffffffu, s, o);

    float inv = __frcp_rn(s);
    bf162 h0 = __float22bfloat162_rn(make_float2(v.x * inv, v.y * inv));
    bf162 h1 = __float22bfloat162_rn(make_float2(v.z * inv, v.w * inv));
    bf162* ob = reinterpret_cast<bf162*>(g_pb + (size_t)row * HW);
    ob[tid * 2]     = h0;
    ob[tid * 2 + 1] = h1;
}

// ======================= bf16 mma.sync GEMM core (BK=64) =====================
// out[m][n] = sum_k A[m][k] * B[n][k]  (NT, both K-contiguous, bf16)
// Block tile 128x128, BK=64, 3-stage cp.async, 8 warps (2x4), warp 64x32.
// Fragment stream: double-buffered (prefetch s4+1 during s4 mma), B via x4.

#define BKH   72                 // 64 + 8 pad halves; 144B row stride (36 words)
#define STGB  (128 * BKH * 2)    // bytes per stage (A or B)
#define VKH   136                // V tile: 128 + 8 pad halves; 272B stride
#define VSTGB (64 * VKH * 2)     // bytes per V stage
#define NSTG  3
#define SMEM_DYN (2 * NSTG * STGB)   // 110592 bytes

__device__ __forceinline__ void cp16(unsigned dst, const void* src) {
    asm volatile("cp.async.cg.shared.global [%0], [%1], 16;\n" :: "r"(dst), "l"(src));
}
__device__ __forceinline__ void cp_commit() { asm volatile("cp.async.commit_group;\n"); }
__device__ __forceinline__ void cp_wait1()  { asm volatile("cp.async.wait_group 1;\n"); }

__device__ __forceinline__ void ldsm_x4(unsigned* r, unsigned addr) {
    asm volatile("ldmatrix.sync.aligned.m8n8.x4.shared.b16 {%0,%1,%2,%3}, [%4];"
                 : "=r"(r[0]), "=r"(r[1]), "=r"(r[2]), "=r"(r[3]) : "r"(addr));
}
__device__ __forceinline__ void ldsm_x4t(unsigned* r, unsigned addr) {
    asm volatile("ldmatrix.sync.aligned.m8n8.x4.trans.shared.b16 {%0,%1,%2,%3}, [%4];"
                 : "=r"(r[0]), "=r"(r[1]), "=r"(r[2]), "=r"(r[3]) : "r"(addr));
}

__device__ __forceinline__ void mma_bf16(float c[4],
                                         unsigned a0, unsigned a1, unsigned a2, unsigned a3,
                                         unsigned b0, unsigned b1) {
    asm volatile(
        "mma.sync.aligned.m16n8k16.row.col.f32.bf16.bf16.f32 "
        "{%0,%1,%2,%3},{%4,%5,%6,%7},{%8,%9},{%0,%1,%2,%3};\n"
        : "+f"(c[0]), "+f"(c[1]), "+f"(c[2]), "+f"(c[3])
        : "r"(a0), "r"(a1), "r"(a2), "r"(a3), "r"(b0), "r"(b1));
}

// fragment loaders: s4 in [0,4) selects the k16 step inside the K=64 block
__device__ __forceinline__ void nt_frags(unsigned aStage, unsigned bStage, int s4,
                                         unsigned af[4][4], unsigned bf[4][2]) {
    #pragma unroll
    for (int mi = 0; mi < 4; mi++)
        ldsm_x4(af[mi], aStage + (unsigned)((mi * 16 * BKH + s4 * 16) * 2));
    #pragma unroll
    for (int pr = 0; pr < 2; pr++) {
        unsigned r[4];
        ldsm_x4(r, bStage + (unsigned)((pr * 16 * BKH + s4 * 16) * 2));
        bf[2 * pr][0] = r[0]; bf[2 * pr][1] = r[1];
        bf[2 * pr + 1][0] = r[2]; bf[2 * pr + 1][1] = r[3];
    }
}

__device__ __forceinline__ void pv_frags(unsigned aStage, unsigned bStage, int s4,
                                         unsigned af[4][4], unsigned bf[4][2]) {
    #pragma unroll
    for (int mi = 0; mi < 4; mi++)
        ldsm_x4(af[mi], aStage + (unsigned)((mi * 16 * BKH + s4 * 16) * 2));
    #pragma unroll
    for (int pr = 0; pr < 2; pr++) {
        unsigned r[4];
        ldsm_x4t(r, bStage + (unsigned)((s4 * 16 * VKH + pr * 16) * 2));
        bf[2 * pr][0] = r[0]; bf[2 * pr][1] = r[1];
        bf[2 * pr + 1][0] = r[2]; bf[2 * pr + 1][1] = r[3];
    }
}

#define MMA_TILE(accv, afv, bfv) \
    _Pragma("unroll") \
    for (int mi = 0; mi < 4; mi++) \
        _Pragma("unroll") \
        for (int ni = 0; ni < 4; ni++) \
            mma_bf16((accv)[mi][ni], (afv)[mi][0], (afv)[mi][1], (afv)[mi][2], (afv)[mi][3], \
                     (bfv)[ni][0], (bfv)[ni][1]);

// ---- NT core: A and B both [row][k] K-contiguous, 128 rows each ------------
__device__ __forceinline__ void gemm_nt(const bf16* __restrict__ A,
                                        const bf16* __restrict__ B,
                                        int lda, int ldb, int K,
                                        unsigned aS, unsigned bS,
                                        float acc[4][4][4]) {
    const int tid = threadIdx.x, lane = tid & 31, warp = tid >> 5;
    const int wm = (warp >> 2) * 64, wn = (warp & 3) * 32;

    const int row = tid >> 3, q = tid & 7;   // + i*32 rows per chunk
    const bf16* Ap = A + (size_t)row * lda + q * 8;
    const bf16* Bp = B + (size_t)row * ldb + q * 8;
    const unsigned aD = aS + (unsigned)((row * BKH + q * 8) * 2);
    const unsigned bD = bS + (unsigned)((row * BKH + q * 8) * 2);

    const unsigned aL  = (unsigned)(((wm + (lane & 15)) * BKH + (lane >> 4) * 8) * 2);
    // B x4 lanes: 0-7 rows n0..7 klo, 8-15 rows n0..7 khi, 16-23 rows n8..15 klo, 24-31 khi
    const unsigned bL4 = (unsigned)(((wn + (lane & 7) + ((lane >> 4) << 3)) * BKH
                                     + ((lane >> 3) & 1) * 8) * 2);

    const int n_iter = K >> 6;

    #pragma unroll
    for (int s = 0; s < 2; s++) {
        const int k0 = s << 6;
        #pragma unroll
        for (int i = 0; i < 4; i++) {
            cp16(aD + s * STGB + i * (32 * BKH * 2), Ap + (size_t)i * 32 * lda + k0);
            cp16(bD + s * STGB + i * (32 * BKH * 2), Bp + (size_t)i * 32 * ldb + k0);
        }
        cp_commit();
    }

    int st = 0, pst = 2;
    for (int it = 0; it < n_iter; it++) {
        cp_wait1();
        __syncthreads();

        if (it + 2 < n_iter) {
            const int k0 = (it + 2) << 6;
            #pragma unroll
            for (int i = 0; i < 4; i++) {
                cp16(aD + pst * STGB + i * (32 * BKH * 2), Ap + (size_t)i * 32 * lda + k0);
                cp16(bD + pst * STGB + i * (32 * BKH * 2), Bp + (size_t)i * 32 * ldb + k0);
            }
        }
        cp_commit();

        const unsigned aStage = aS + st * STGB + aL;
        const unsigned bStage = bS + st * STGB + bL4;

        unsigned af[2][4][4], bf[2][4][2];
        nt_frags(aStage, bStage, 0, af[0], bf[0]);
        #pragma unroll
        for (int s4 = 0; s4 < 4; s4++) {
            const int cur = s4 & 1;
            if (s4 < 3)
                nt_frags(aStage, bStage, s4 + 1, af[cur ^ 1], bf[cur ^ 1]);
            MMA_TILE(acc, af[cur], bf[cur]);
        }
        st  = (st  == NSTG - 1) ? 0 : st + 1;
        pst = (pst == NSTG - 1) ? 0 : pst + 1;
    }
}

// ---- PV core: A = P [row][k]; B = V [k][n] native layout, trans-ldmatrix ---
__device__ __forceinline__ void gemm_pv(const bf16* __restrict__ A,
                                        const bf16* __restrict__ V,   // + n0 offset
                                        int lda, int ldv, int K,
                                        unsigned aS, unsigned bS,
                                        float acc[4][4][4]) {
    const int tid = threadIdx.x, lane = tid & 31, warp = tid >> 5;
    const int wm = (warp >> 2) * 64, wn = (warp & 3) * 32;

    const int row = tid >> 3, q = tid & 7;
    const bf16* Ap = A + (size_t)row * lda + q * 8;
    const unsigned aD = aS + (unsigned)((row * BKH + q * 8) * 2);

    const int vrow = tid >> 4, vq = tid & 15;   // + i*16 rows per chunk
    const bf16* Vp = V + (size_t)vrow * ldv + vq * 8;
    const unsigned vD = bS + (unsigned)((vrow * VKH + vq * 8) * 2);

    const unsigned aL   = (unsigned)(((wm + (lane & 15)) * BKH + (lane >> 4) * 8) * 2);
    // trans x4: lanes 0-15 rows k0..15 at col base; lanes 16-31 same rows col +8
    const unsigned bLT4 = (unsigned)(((lane & 15) * VKH + wn + ((lane >> 4) << 3)) * 2);

    const int n_iter = K >> 6;

    #pragma unroll
    for (int s = 0; s < 2; s++) {
        const int k0 = s << 6;
        #pragma unroll
        for (int i = 0; i < 4; i++) {
            cp16(aD + s * STGB  + i * (32 * BKH * 2), Ap + (size_t)i * 32 * lda + k0);
            cp16(vD + s * VSTGB + i * (16 * VKH * 2), Vp + (size_t)(k0 + i * 16) * ldv);
        }
        cp_commit();
    }

    int st = 0, pst = 2;
    for (int it = 0; it < n_iter; it++) {
        cp_wait1();
        __syncthreads();

        if (it + 2 < n_iter) {
            const int k0 = (it + 2) << 6;
            #pragma unroll
            for (int i = 0; i < 4; i++) {
                cp16(aD + pst * STGB  + i * (32 * BKH * 2), Ap + (size_t)i * 32 * lda + k0);
                cp16(vD + pst * VSTGB + i * (16 * VKH * 2), Vp + (size_t)(k0 + i * 16) * ldv);
            }
        }
        cp_commit();

        const unsigned aStage = aS + st * STGB + aL;
        const unsigned bStage = bS + st * VSTGB + bLT4;

        unsigned af[2][4][4], bf[2][4][2];
        pv_frags(aStage, bStage, 0, af[0], bf[0]);
        #pragma unroll
        for (int s4 = 0; s4 < 4; s4++) {
            const int cur = s4 & 1;
            if (s4 < 3)
                pv_frags(aStage, bStage, s4 + 1, af[cur ^ 1], bf[cur ^ 1]);
            MMA_TILE(acc, af[cur], bf[cur]);
        }
        st  = (st  == NSTG - 1) ? 0 : st + 1;
        pst = (pst == NSTG - 1) ? 0 : pst + 1;
    }
}

#define GEMM_PREAMBLE() \
    extern __shared__ char dynraw[]; \
    const unsigned smb = (unsigned)__cvta_generic_to_shared(dynraw); \
    const unsigned aS = smb; \
    const unsigned bS = smb + NSTG * STGB; \
    const int tid = threadIdx.x, lane = tid & 31, warp = tid >> 5; \
    const int g = lane >> 2, tig = lane & 3; \
    const int wm = (warp >> 2) * 64, wn = (warp & 3) * 32;

// ---------------- GEMM 1: QKV projections (bf16 out) ------------------------
__global__ void __launch_bounds__(256, 2) k_qkv(
        const float* __restrict__ bq, const float* __restrict__ bk,
        const float* __restrict__ bv) {
    GEMM_PREAMBLE();
    const bf16* W; const float* Bi; bf16* out;
    if (blockIdx.z == 0)      { W = g_wq; Bi = bq; out = g_q; }
    else if (blockIdx.z == 1) { W = g_wk; Bi = bk; out = g_k; }
    else                      { W = g_wv; Bi = bv; out = g_v; }
    const int m0 = blockIdx.x * 128;   // token
    const int n0 = blockIdx.y * 128;   // out channel
    float acc[4][4][4] = {};
    gemm_nt(g_hn + (size_t)m0 * C_DIM, W + (size_t)n0 * C_DIM, C_DIM, C_DIM, C_DIM,
            aS, bS, acc);

    #pragma unroll
    for (int mi = 0; mi < 4; mi++) {
        int r0 = m0 + wm + mi * 16 + g;
        #pragma unroll
        for (int ni = 0; ni < 4; ni++) {
            int c = n0 + wn + ni * 8 + 2 * tig;
            float b0v = Bi[c], b1v = Bi[c + 1];
            *reinterpret_cast<bf162*>(&out[(size_t)r0 * C_DIM + c]) =
                __float22bfloat162_rn(make_float2(acc[mi][ni][0] + b0v, acc[mi][ni][1] + b1v));
            *reinterpret_cast<bf162*>(&out[(size_t)(r0 + 8) * C_DIM + c]) =
                __float22bfloat162_rn(make_float2(acc[mi][ni][2] + b0v, acc[mi][ni][3] + b1v));
        }
    }
}

// ---------------- GEMM 2: S = scale * Q K^T (fp32 out) ----------------------
__global__ void __launch_bounds__(256, 2) k_qk(float scale) {
    GEMM_PREAMBLE();
    const int f  = blockIdx.z;
    const int m0 = blockIdx.x * 128;
    const int n0 = blockIdx.y * 128;
    const bf16* Q  = g_q + (size_t)f * HW * C_DIM + (size_t)m0 * C_DIM;
    const bf16* Km = g_k + (size_t)f * HW * C_DIM + (size_t)n0 * C_DIM;
    float* P = g_p + (size_t)f * HW * HW;
    float acc[4][4][4] = {};
    gemm_nt(Q, Km, C_DIM, C_DIM, C_DIM, aS, bS, acc);

    #pragma unroll
    for (int mi = 0; mi < 4; mi++) {
        int r0 = m0 + wm + mi * 16 + g;
        #pragma unroll
        for (int ni = 0; ni < 4; ni++) {
            int c = n0 + wn + ni * 8 + 2 * tig;
            *reinterpret_cast<float2*>(&P[(size_t)r0 * HW + c]) =
                make_float2(acc[mi][ni][0] * scale, acc[mi][ni][1] * scale);
            *reinterpret_cast<float2*>(&P[(size_t)(r0 + 8) * HW + c]) =
                make_float2(acc[mi][ni][2] * scale, acc[mi][ni][3] * scale);
        }
    }
}

// ---------------- GEMM 3: O = P V (bf16 out, V native layout) ---------------
__global__ void __launch_bounds__(256, 2) k_pv() {
    GEMM_PREAMBLE();
    const int f  = blockIdx.z;
    const int m0 = blockIdx.x * 128;   // query token
    const int n0 = blockIdx.y * 128;   // channel
    const bf16* P = g_pb + (size_t)f * HW * HW + (size_t)m0 * HW;
    const bf16* V = g_v  + (size_t)f * HW * C_DIM + n0;
    float acc[4][4][4] = {};
    gemm_pv(P, V, HW, C_DIM, HW, aS, bS, acc);

    bf16* O = g_ao + (size_t)f * HW * C_DIM;
    #pragma unroll
    for (int mi = 0; mi < 4; mi++) {
        int r0 = m0 + wm + mi * 16 + g;
        #pragma unroll
        for (int ni = 0; ni < 4; ni++) {
            int c = n0 + wn + ni * 8 + 2 * tig;
            *reinterpret_cast<bf162*>(&O[(size_t)r0 * C_DIM + c]) =
                __float22bfloat162_rn(make_float2(acc[mi][ni][0], acc[mi][ni][1]));
            *reinterpret_cast<bf162*>(&O[(size_t)(r0 + 8) * C_DIM + c]) =
                __float22bfloat162_rn(make_float2(acc[mi][ni][2], acc[mi][ni][3]));
        }
    }
}

// ---------------- GEMM 4: out proj + bias + residual (fp32 out) -------------
__global__ void __launch_bounds__(256, 2) k_out(
        const float* __restrict__ bo,
        const float* __restrict__ x, float* __restrict__ y) {
    GEMM_PREAMBLE();
    const int m0 = blockIdx.x * 128;   // out channel
    const int n0 = blockIdx.y * 128;   // spatial position
    float acc[4][4][4] = {};
    gemm_nt(g_wo + (size_t)m0 * C_DIM, g_ao + (size_t)n0 * C_DIM, C_DIM, C_DIM, C_DIM,
            aS, bS, acc);

    #pragma unroll
    for (int mi = 0; mi < 4; mi++) {
        int r0 = m0 + wm + mi * 16 + g;
        float bo0 = bo[r0], bo1 = bo[r0 + 8];
        #pragma unroll
        for (int ni = 0; ni < 4; ni++) {
            int c = n0 + wn + ni * 8 + 2 * tig;
            size_t i00 = (size_t)r0 * S_TOT + c;
            size_t i10 = (size_t)(r0 + 8) * S_TOT + c;
            float2 x0 = *reinterpret_cast<const float2*>(&x[i00]);
            float2 x1 = *reinterpret_cast<const float2*>(&x[i10]);
            *reinterpret_cast<float2*>(&y[i00]) =
                make_float2(acc[mi][ni][0] + bo0 + x0.x, acc[mi][ni][1] + bo0 + x0.y);
            *reinterpret_cast<float2*>(&y[i10]) =
                make_float2(acc[mi][ni][2] + bo1 + x1.x, acc[mi][ni][3] + bo1 + x1.y);
        }
    }
}

// ---------------- launch ------------------------------------------------------
extern "C" void kernel_launch(void* const* d_in, const int* in_sizes, int n_in,
                              void* d_out, int out_size) {
    const float* x     = (const float*)d_in[0];
    const float* gamma = (const float*)d_in[1];
    const float* beta  = (const float*)d_in[2];
    const float* wq    = (const float*)d_in[3];
    const float* bq    = (const float*)d_in[4];
    const float* wk    = (const float*)d_in[5];
    const float* bk    = (const float*)d_in[6];
    const float* wv    = (const float*)d_in[7];
    const float* bv    = (const float*)d_in[8];
    const float* wo    = (const float*)d_in[9];
    const float* bo    = (const float*)d_in[10];
    float* y = (float*)d_out;

    cudaFuncSetAttribute(k_qkv, cudaFuncAttributeMaxDynamicSharedMemorySize, SMEM_DYN);
    cudaFuncSetAttribute(k_qk,  cudaFuncAttributeMaxDynamicSharedMemorySize, SMEM_DYN);
    cudaFuncSetAttribute(k_pv,  cudaFuncAttributeMaxDynamicSharedMemorySize, SMEM_DYN);
    cudaFuncSetAttribute(k_out, cudaFuncAttributeMaxDynamicSharedMemorySize, SMEM_DYN);

    w_convert<<<dim3(256, 4), 256>>>(wq, wk, wv, wo);
    gn_stats1<<<dim3(NG, 8), 256>>>(x);
    gn_stats2<<<1, 32>>>();
    gn_apply_t<<<dim3(S_TOT / 32, C_DIM / 32), dim3(32, 8)>>>(x, gamma, beta);

    k_qkv<<<dim3(S_TOT / 128, C_DIM / 128, 3), 256, SMEM_DYN>>>(bq, bk, bv);

    const float scale = 0.044194173824159216f;  // 512^-0.5
    k_qk<<<dim3(HW / 128, HW / 128, T_FR), 256, SMEM_DYN>>>(scale);

    softmax_rows<<<S_TOT, 256>>>();

    k_pv<<<dim3(HW / 128, C_DIM / 128, T_FR), 256, SMEM_DYN>>>();

    k_out<<<dim3(C_DIM / 128, S_TOT / 128), 256, SMEM_DYN>>>(bo, x, y);
}